// round 4
// baseline (speedup 1.0000x reference)
#include <cuda_runtime.h>
#include <cuda_bf16.h>
#include <stdint.h>

// Embedding_44994077393181
// out[b,t,:] = W_emb_tok[ argnz(X[b,t,:]) , : ] + X_emb_pos[t,:]
// X: (2,2048,32000) fp32 one-hot; W: (32000,1024) fp32; pos: (2048,1024) fp32
// One CTA (128 threads = 4 warps) per (b,t) row. BARRIER-FREE early-exit scan:
// warps free-run round-robin over 512-float chunks (4 independent float4 per
// thread per pass), polling a volatile shared flag at pass boundaries instead
// of lock-stepping with __syncthreads. Then fused gather + positional add.

#define VOCAB   32000
#define EMB_DIM 1024
#define CTX     2048
#define NROWS   4096          // BATCH * CTX
#define THREADS 128
#define NWARP   4
#define WCHUNK  512           // floats per warp-pass = 32 lanes * 4 float4
#define NPASS   63            // ceil(32000 / 512)

__global__ __launch_bounds__(THREADS)
void embed_onehot_kernel(const float* __restrict__ X,
                         const float* __restrict__ W,
                         const float* __restrict__ pos,
                         float* __restrict__ out)
{
    const int row  = blockIdx.x;           // 0..4095  (b = row / CTX, t = row % CTX)
    const int t    = row & (CTX - 1);
    const int tid  = threadIdx.x;
    const int wid  = tid >> 5;
    const int lane = tid & 31;

    const float* xrow = X + (size_t)row * VOCAB;

    __shared__ int s_idx;
    if (tid == 0) s_idx = -1;
    __syncthreads();

    volatile int* flag = &s_idx;

    // Free-running warp round-robin scan. Warp w scans chunks w, w+4, w+8, ...
    // Exactly one nonzero per row -> single writer to s_idx, no race.
    #pragma unroll 1
    for (int pass = wid; pass < NPASS; pass += NWARP) {
        if (*flag >= 0) break;             // another warp already found it
        const int base = pass * WCHUNK;
        int found = -1;
        #pragma unroll
        for (int j = 0; j < 4; ++j) {
            const int i = base + ((j * 32 + lane) << 2);
            if (i < VOCAB) {
                const float4 v = __ldcs(reinterpret_cast<const float4*>(xrow + i));
                if (v.x != 0.0f) found = i;
                if (v.y != 0.0f) found = i + 1;
                if (v.z != 0.0f) found = i + 2;
                if (v.w != 0.0f) found = i + 3;
            }
        }
        if (found >= 0) {
            s_idx = found;
            break;
        }
    }

    // Single barrier: covers the case where a warp exhausts its passes before
    // the finder writes, and makes s_idx visible to all warps for the gather.
    __syncthreads();
    const int idx = s_idx;

    // Fused gather + positional add: 1024 floats = 128 threads * 2 float4.
    const float4* wrow = reinterpret_cast<const float4*>(W   + (size_t)idx * EMB_DIM);
    const float4* prow = reinterpret_cast<const float4*>(pos + (size_t)t   * EMB_DIM);
    float4*       orow = reinterpret_cast<float4*>(out + (size_t)row * EMB_DIM);

    #pragma unroll
    for (int j = 0; j < 2; ++j) {
        const int c = j * THREADS + tid;
        const float4 wv = __ldg(wrow + c);
        const float4 pv = __ldg(prow + c);
        float4 o;
        o.x = wv.x + pv.x;
        o.y = wv.y + pv.y;
        o.z = wv.z + pv.z;
        o.w = wv.w + pv.w;
        orow[c] = o;
    }
}

extern "C" void kernel_launch(void* const* d_in, const int* in_sizes, int n_in,
                              void* d_out, int out_size)
{
    const float* X   = (const float*)d_in[0];   // (2,2048,32000)
    const float* W   = (const float*)d_in[1];   // (32000,1024)
    const float* pos = (const float*)d_in[2];   // (2048,1024)
    float* out = (float*)d_out;                 // (2,2048,1024)

    embed_onehot_kernel<<<NROWS, THREADS>>>(X, W, pos, out);
}

// round 5
// speedup vs baseline: 1.0011x; 1.0011x over previous
#include <cuda_runtime.h>
#include <cuda_bf16.h>
#include <stdint.h>

// Embedding_44994077393181
// out[b,t,:] = W_emb_tok[ argnz(X[b,t,:]) , : ] + X_emb_pos[t,:]
// X: (2,2048,32000) fp32 one-hot; W: (32000,1024) fp32; pos: (2048,1024) fp32
//
// One CTA (128 threads) per (b,t) row. Lock-step early-exit scan in 1024-float
// chunks, SOFTWARE-PIPELINED one chunk ahead: pass p+1's loads are issued
// before pass p's check + barrier, so the per-pass __syncthreads_or never
// exposes an idle memory pipe. Overshoot bounded at exactly +1 chunk.
// Then fused gather + positional add.

#define VOCAB   32000
#define EMB_DIM 1024
#define CTX     2048
#define NROWS   4096          // BATCH * CTX
#define THREADS 128
#define CHUNK   1024          // floats per pass = 256 float4 = 128 threads * 2
#define NFULL   31            // full chunks (31*1024 = 31744), tail = 256 floats

__global__ __launch_bounds__(THREADS)
void embed_onehot_kernel(const float* __restrict__ X,
                         const float* __restrict__ W,
                         const float* __restrict__ pos,
                         float* __restrict__ out)
{
    const int row = blockIdx.x;            // 0..4095  (b = row / CTX, t = row % CTX)
    const int t   = row & (CTX - 1);
    const int tid = threadIdx.x;

    const float4* xv = reinterpret_cast<const float4*>(X + (size_t)row * VOCAB);

    __shared__ int s_idx;                  // written by exactly one thread (one-hot)

    // Prologue: loads for chunk 0 (thread tid covers float4 slots tid and 128+tid).
    float4 a0 = __ldcs(xv + tid);
    float4 a1 = __ldcs(xv + 128 + tid);

    bool found_any = false;

    #pragma unroll 1
    for (int pass = 0; pass < NFULL; ++pass) {
        // Issue next chunk's loads BEFORE checking current regs / barrier.
        float4 b0, b1;
        if (pass < NFULL - 1) {
            const int nb = (pass + 1) * 256;
            b0 = __ldcs(xv + nb + tid);
            b1 = __ldcs(xv + nb + 128 + tid);
        }

        // Check current chunk. a0 -> elements [i0, i0+3], a1 -> [i0+512, i0+515].
        const int i0 = pass * CHUNK + (tid << 2);
        int found = -1;
        if (a0.x != 0.0f) found = i0;
        if (a0.y != 0.0f) found = i0 + 1;
        if (a0.z != 0.0f) found = i0 + 2;
        if (a0.w != 0.0f) found = i0 + 3;
        if (a1.x != 0.0f) found = i0 + 512;
        if (a1.y != 0.0f) found = i0 + 513;
        if (a1.z != 0.0f) found = i0 + 514;
        if (a1.w != 0.0f) found = i0 + 515;

        if (found >= 0) s_idx = found;     // single writer, pre-barrier
        if (__syncthreads_or(found >= 0)) { found_any = true; break; }

        a0 = b0;
        a1 = b1;
    }

    // Tail: elements [31744, 32000) = 64 float4, threads 0..63. (~0.8% of rows)
    if (!found_any) {
        int found = -1;
        if (tid < 64) {
            const float4 v = __ldcs(xv + 7936 + tid);
            const int i = 31744 + (tid << 2);
            if (v.x != 0.0f) found = i;
            if (v.y != 0.0f) found = i + 1;
            if (v.z != 0.0f) found = i + 2;
            if (v.w != 0.0f) found = i + 3;
        }
        if (found >= 0) s_idx = found;
    }

    __syncthreads();                       // make s_idx visible to all warps
    const int idx = s_idx;

    // Fused gather + positional add: 1024 floats = 128 threads * 2 float4.
    const float4* wrow = reinterpret_cast<const float4*>(W   + (size_t)idx * EMB_DIM);
    const float4* prow = reinterpret_cast<const float4*>(pos + (size_t)t   * EMB_DIM);
    float4*       orow = reinterpret_cast<float4*>(out + (size_t)row * EMB_DIM);

    #pragma unroll
    for (int j = 0; j < 2; ++j) {
        const int c = j * THREADS + tid;
        const float4 wv = __ldg(wrow + c);
        const float4 pv = __ldg(prow + c);
        float4 o;
        o.x = wv.x + pv.x;
        o.y = wv.y + pv.y;
        o.z = wv.z + pv.z;
        o.w = wv.w + pv.w;
        orow[c] = o;
    }
}

extern "C" void kernel_launch(void* const* d_in, const int* in_sizes, int n_in,
                              void* d_out, int out_size)
{
    const float* X   = (const float*)d_in[0];   // (2,2048,32000)
    const float* W   = (const float*)d_in[1];   // (32000,1024)
    const float* pos = (const float*)d_in[2];   // (2048,1024)
    float* out = (float*)d_out;                 // (2,2048,1024)

    embed_onehot_kernel<<<NROWS, THREADS>>>(X, W, pos, out);
}